// round 2
// baseline (speedup 1.0000x reference)
#include <cuda_runtime.h>
#include <cuda_bf16.h>
#include <math.h>

// Problem constants
#define B_SZ   8192
#define XCOLS  145     // IN_F + LAT + 1
#define IN_F   16
#define LAT    128
#define HID    1024
#define CS     6540    // (M+2)*K
#define MK     6528    // M*K
#define KF     6       // K (fourier terms)

// ---------------- scratch (static device globals; no allocation) ------------
__device__ float g_h1[(size_t)B_SZ * HID];     // 33.5 MB
__device__ float g_h2[(size_t)B_SZ * CS];      // 214 MB
__device__ float g_cc[(size_t)B_SZ * MK];      // 214 MB (v-scaled coeffs)
__device__ float g_v [(size_t)B_SZ * KF];

// ---------------- generic tiled SGEMM: C = epilogue(A@B + bias) -------------
// mode 0: +bias ; mode 1: tanh(+bias) ; mode 2: (+bias) * v[row, col%6]
#define BM 128
#define BN 128
#define BK 16
#define TM 8
#define TN 8

__global__ __launch_bounds__(256, 2)
void sgemm_k(const float* __restrict__ A, int lda,
             const float* __restrict__ Bm, int ldb,
             const float* __restrict__ bias,
             const float* __restrict__ vsc,
             float* __restrict__ C, int ldc,
             int Ndim, int Kdim, int mode)
{
    __shared__ float As[BK][BM + 4];
    __shared__ float Bs[BK][BN + 4];

    const int tid = threadIdx.x;
    const int bm  = blockIdx.y * BM;
    const int bn  = blockIdx.x * BN;
    const int tx  = tid % 16;           // 16 col groups
    const int ty  = tid / 16;           // 16 row groups

    float acc[TM][TN];
    #pragma unroll
    for (int i = 0; i < TM; ++i)
        #pragma unroll
        for (int j = 0; j < TN; ++j) acc[i][j] = 0.f;

    for (int k0 = 0; k0 < Kdim; k0 += BK) {
        // load A tile (BM x BK), consecutive tids -> consecutive k
        #pragma unroll
        for (int i = 0; i < (BM * BK) / 256; ++i) {
            int idx = tid + i * 256;
            int m = idx / BK, k = idx % BK;
            float val = 0.f;
            if (k0 + k < Kdim)
                val = A[(size_t)(bm + m) * lda + k0 + k];
            As[k][m] = val;
        }
        // load B tile (BK x BN), fully coalesced in n
        #pragma unroll
        for (int i = 0; i < (BK * BN) / 256; ++i) {
            int idx = tid + i * 256;
            int k = idx / BN, n = idx % BN;
            float val = 0.f;
            if (k0 + k < Kdim && bn + n < Ndim)
                val = Bm[(size_t)(k0 + k) * ldb + bn + n];
            Bs[k][n] = val;
        }
        __syncthreads();

        #pragma unroll
        for (int k = 0; k < BK; ++k) {
            float ra[TM], rb[TN];
            float4 a0 = *reinterpret_cast<const float4*>(&As[k][ty * TM]);
            float4 a1 = *reinterpret_cast<const float4*>(&As[k][ty * TM + 4]);
            float4 b0 = *reinterpret_cast<const float4*>(&Bs[k][tx * TN]);
            float4 b1 = *reinterpret_cast<const float4*>(&Bs[k][tx * TN + 4]);
            ra[0]=a0.x; ra[1]=a0.y; ra[2]=a0.z; ra[3]=a0.w;
            ra[4]=a1.x; ra[5]=a1.y; ra[6]=a1.z; ra[7]=a1.w;
            rb[0]=b0.x; rb[1]=b0.y; rb[2]=b0.z; rb[3]=b0.w;
            rb[4]=b1.x; rb[5]=b1.y; rb[6]=b1.z; rb[7]=b1.w;
            #pragma unroll
            for (int i = 0; i < TM; ++i)
                #pragma unroll
                for (int j = 0; j < TN; ++j)
                    acc[i][j] = fmaf(ra[i], rb[j], acc[i][j]);
        }
        __syncthreads();
    }

    #pragma unroll
    for (int i = 0; i < TM; ++i) {
        int row = bm + ty * TM + i;
        #pragma unroll
        for (int j = 0; j < TN; ++j) {
            int col = bn + tx * TN + j;
            if (col < Ndim) {
                float val = acc[i][j] + bias[col];
                if (mode == 1)      val = tanhf(val);
                else if (mode == 2) val *= vsc[(size_t)row * KF + (col % KF)];
                C[(size_t)row * ldc + col] = val;
            }
        }
    }
}

// -------- tail: d[j] = h2[b]·W3[:,6528+j] + b3[6528+j]  ->  v[b,0..5] --------
__global__ __launch_bounds__(128)
void tail_v_kernel(const float* __restrict__ h2,
                   const float* __restrict__ W3,
                   const float* __restrict__ b3,
                   const float* __restrict__ x,
                   float* __restrict__ v)
{
    const int b = blockIdx.x;
    const int t = threadIdx.x;  // 128
    float p[12];
    #pragma unroll
    for (int j = 0; j < 12; ++j) p[j] = 0.f;

    const float* hrow = h2 + (size_t)b * CS;
    for (int c = t; c < CS; c += 128) {
        float hv = hrow[c];
        const float* wr = W3 + (size_t)c * CS + MK;
        #pragma unroll
        for (int j = 0; j < 12; ++j) p[j] = fmaf(hv, wr[j], p[j]);
    }

    __shared__ float red[128];
    __shared__ float dtail[12];
    for (int j = 0; j < 12; ++j) {
        red[t] = p[j];
        __syncthreads();
        for (int s = 64; s > 0; s >>= 1) {
            if (t < s) red[t] += red[t + s];
            __syncthreads();
        }
        if (t == 0) dtail[j] = red[0] + b3[MK + j];
        __syncthreads();
    }

    if (t < 6) {
        float s  = x[(size_t)(B_SZ - 1) * XCOLS + IN_F];  // scalar from input
        float sv = fmaf(s, dtail[t], dtail[t + 6]);
        float r  = (t < 3) ? cosf(sv * (float)t) : sinf(sv * (float)(t - 3));
        v[(size_t)b * KF + t] = r;
    }
}

// -------- final: out[b,o] = sum_i inp[b,i]*sum6(cc[(i*64+o)*6..]) + sum6(cc[(1024+o)*6..])
__global__ __launch_bounds__(256)
void final_kernel(const float* __restrict__ cc,
                  const float* __restrict__ x,
                  float* __restrict__ out)
{
    const int b = blockIdx.x;
    const int t = threadIdx.x;  // 256
    __shared__ float row[MK];
    __shared__ float inp[IN_F];

    const float* src = cc + (size_t)b * MK;
    for (int i = t; i < MK; i += 256) row[i] = src[i];
    if (t < IN_F) inp[t] = x[(size_t)b * XCOLS + t];
    __syncthreads();

    if (t < 64) {
        const int o = t;
        float accum = 0.f;
        #pragma unroll
        for (int i = 0; i < IN_F; ++i) {
            const float* g = row + (i * 64 + o) * KF;
            float wsum = ((g[0] + g[1]) + (g[2] + g[3])) + (g[4] + g[5]);
            accum = fmaf(inp[i], wsum, accum);
        }
        const float* g = row + (1024 + o) * KF;
        accum += ((g[0] + g[1]) + (g[2] + g[3])) + (g[4] + g[5]);
        out[(size_t)b * 64 + o] = accum;
    }
}

// ----------------------------- launch ---------------------------------------
extern "C" void kernel_launch(void* const* d_in, const int* in_sizes, int n_in,
                              void* d_out, int out_size)
{
    const float* x  = (const float*)d_in[0];
    const float* W1 = (const float*)d_in[1];
    const float* b1 = (const float*)d_in[2];
    const float* W2 = (const float*)d_in[3];
    const float* b2 = (const float*)d_in[4];
    const float* W3 = (const float*)d_in[5];
    const float* b3 = (const float*)d_in[6];
    float* out = (float*)d_out;

    float *h1, *h2, *cc, *v;
    cudaGetSymbolAddress((void**)&h1, g_h1);
    cudaGetSymbolAddress((void**)&h2, g_h2);
    cudaGetSymbolAddress((void**)&cc, g_cc);
    cudaGetSymbolAddress((void**)&v,  g_v);

    // 1) h1 = tanh(z @ W1 + b1)   z = x[:, 17:145], lda = 145
    sgemm_k<<<dim3(HID / BN, B_SZ / BM), 256>>>(
        x + (IN_F + 1), XCOLS, W1, HID, b1, nullptr, h1, HID,
        HID, LAT, /*mode=*/1);

    // 2) h2 = tanh(h1 @ W2 + b2)
    sgemm_k<<<dim3((CS + BN - 1) / BN, B_SZ / BM), 256>>>(
        h1, HID, W2, CS, b2, nullptr, h2, CS,
        CS, HID, /*mode=*/1);

    // 3) tail 12 columns -> v[b, 0..5]
    tail_v_kernel<<<B_SZ, 128>>>(h2, W3, b3, x, v);

    // 4) big GEMM: cc[b,n] = (h2[b]·W3[:,n] + b3[n]) * v[b, n%6], n < 6528
    sgemm_k<<<dim3(MK / BN, B_SZ / BM), 256>>>(
        h2, CS, W3, CS, b3, v, cc, MK,
        MK, CS, /*mode=*/2);

    // 5) fused group-of-6 sum + adaptive 16->64 linear
    final_kernel<<<B_SZ, 256>>>(cc, x, out);
}

// round 4
// speedup vs baseline: 2.5329x; 2.5329x over previous
#include <cuda_runtime.h>
#include <cuda_bf16.h>
#include <math.h>
#include <stdint.h>

// ---------------- problem constants ----------------
#define B_SZ   8192
#define XCOLS  145
#define IN_F   16
#define LAT    128
#define HID    1024
#define CS     6540     // (M+2)*K
#define CSP    6656     // CS padded to 256
#define MK     6528     // M*K
#define MK5    5440     // compacted (drop k%6==3, v==0)
#define MK5P   5632     // padded to 256

// ---------------- scratch (zero-initialized device globals) -----------------
__device__ __nv_bfloat16 g_h1hi[(size_t)B_SZ * HID];
__device__ __nv_bfloat16 g_h1lo[(size_t)B_SZ * HID];
__device__ float         g_h2f [(size_t)B_SZ * CS];
__device__ __nv_bfloat16 g_h2hi[(size_t)B_SZ * CSP];   // pads stay zero
__device__ __nv_bfloat16 g_h2lo[(size_t)B_SZ * CSP];
__device__ __nv_bfloat16 g_w2thi[(size_t)CSP * HID];   // W2^T, pad rows zero
__device__ __nv_bfloat16 g_w2tlo[(size_t)CSP * HID];
__device__ __nv_bfloat16 g_w3thi[(size_t)MK5P * CSP];  // W3^T compact, pads zero
__device__ __nv_bfloat16 g_w3tlo[(size_t)MK5P * CSP];
__device__ float         g_cc  [(size_t)B_SZ * MK5];
__device__ float         g_v5  [(size_t)B_SZ * 5];

// ---------------- low-level helpers ----------------
__device__ __forceinline__ uint32_t smem_u32(const void* p) {
    uint32_t a;
    asm("{ .reg .u64 t; cvta.to.shared.u64 t, %1; cvt.u32.u64 %0, t; }" : "=r"(a) : "l"(p));
    return a;
}
__device__ __forceinline__ void cpa16(uint32_t dst, const void* src) {
    asm volatile("cp.async.cg.shared.global [%0], [%1], 16;" :: "r"(dst), "l"(src));
}
#define CP_COMMIT() asm volatile("cp.async.commit_group;" ::: "memory")
#define CP_WAIT2()  asm volatile("cp.async.wait_group 2;" ::: "memory")

__device__ __forceinline__ void ldsm4(uint32_t& r0, uint32_t& r1, uint32_t& r2, uint32_t& r3,
                                      uint32_t addr) {
    asm volatile("ldmatrix.sync.aligned.m8n8.x4.shared.b16 {%0,%1,%2,%3}, [%4];"
                 : "=r"(r0), "=r"(r1), "=r"(r2), "=r"(r3) : "r"(addr));
}
__device__ __forceinline__ void mma_bf16(float* c, const uint32_t* a, uint32_t b0, uint32_t b1) {
    asm volatile(
        "mma.sync.aligned.m16n8k16.row.col.f32.bf16.bf16.f32 "
        "{%0,%1,%2,%3}, {%4,%5,%6,%7}, {%8,%9}, {%0,%1,%2,%3};"
        : "+f"(c[0]), "+f"(c[1]), "+f"(c[2]), "+f"(c[3])
        : "r"(a[0]), "r"(a[1]), "r"(a[2]), "r"(a[3]), "r"(b0), "r"(b1));
}

// ---------------- pipelined bf16x3 GEMM ----------------
// C(128x256 per CTA) = epi( (Ahi+Alo) @ (Bhi+Blo)^T )  via hi*hi + hi*lo + lo*hi
// smem stage: Ahi[128x32] Alo Bhi[256x32] Blo, 80B row stride
#define ROWB    80
#define A_LO_OFF 10240
#define B_HI_OFF 20480
#define B_LO_OFF 40960
#define STG_BYTES 61440
#define GEMM_SMEM (3 * STG_BYTES)

__global__ __launch_bounds__(512, 1)
void mma_gemm(const __nv_bfloat16* __restrict__ Ahi, const __nv_bfloat16* __restrict__ Alo, int lda,
              const __nv_bfloat16* __restrict__ Bhi, const __nv_bfloat16* __restrict__ Blo, int ldb,
              int nk,
              const float* __restrict__ bias, const float* __restrict__ v5,
              float* __restrict__ outf, __nv_bfloat16* __restrict__ outHi,
              __nv_bfloat16* __restrict__ outLo, int ldf, int ldhl,
              int Nlimit, int mode)
{
    extern __shared__ char smem[];
    const uint32_t sbase = smem_u32(smem);
    const int tid  = threadIdx.x;
    const int lane = tid & 31;
    const int wid  = tid >> 5;
    const int warp_m = wid & 3;
    const int warp_n = wid >> 2;
    const int bm = blockIdx.y * 128;
    const int bn = blockIdx.x * 256;

    // per-thread load lanes (A: 128 rows x 4 x 16B; B: 256 rows x 4 x 16B)
    const int lrow = tid >> 2;      // 0..127
    const int lchk = tid & 3;       // 0..3
    const char* aHiSrc = (const char*)(Ahi + (size_t)(bm + lrow) * lda + lchk * 8);
    const char* aLoSrc = (const char*)(Alo + (size_t)(bm + lrow) * lda + lchk * 8);
    const char* bHiSrc0 = (const char*)(Bhi + (size_t)(bn + lrow) * ldb + lchk * 8);
    const char* bLoSrc0 = (const char*)(Blo + (size_t)(bn + lrow) * ldb + lchk * 8);
    const char* bHiSrc1 = (const char*)(Bhi + (size_t)(bn + 128 + lrow) * ldb + lchk * 8);
    const char* bLoSrc1 = (const char*)(Blo + (size_t)(bn + 128 + lrow) * ldb + lchk * 8);
    const uint32_t dA  = lrow * ROWB + lchk * 16;
    const uint32_t dB0 = dA;
    const uint32_t dB1 = dA + 128 * ROWB;

    float acc[2][8][4];
    #pragma unroll
    for (int i = 0; i < 2; ++i)
        #pragma unroll
        for (int j = 0; j < 8; ++j)
            #pragma unroll
            for (int l = 0; l < 4; ++l) acc[i][j][l] = 0.f;

    auto load_stage = [&](int s, int kc) {
        const uint32_t sA = sbase + s * STG_BYTES;
        const size_t kb = (size_t)kc * 64;     // 32 bf16 = 64 bytes per chunk
        cpa16(sA + dA, aHiSrc + kb);
        cpa16(sA + A_LO_OFF + dA, aLoSrc + kb);
        cpa16(sA + B_HI_OFF + dB0, bHiSrc0 + kb);
        cpa16(sA + B_HI_OFF + dB1, bHiSrc1 + kb);
        cpa16(sA + B_LO_OFF + dB0, bLoSrc0 + kb);
        cpa16(sA + B_LO_OFF + dB1, bLoSrc1 + kb);
    };

    // prologue: stages 0,1
    load_stage(0, 0); CP_COMMIT();
    if (nk > 1) load_stage(1, 1);
    CP_COMMIT();

    const int l15  = lane & 15;
    const int lksl = (lane >> 4) & 1;

    for (int k = 0; k < nk; ++k) {
        const int fetch = k + 2;
        if (fetch < nk) load_stage(fetch % 3, fetch);
        CP_COMMIT();
        CP_WAIT2();
        __syncthreads();

        const uint32_t sA = sbase + (k % 3) * STG_BYTES;
        const uint32_t sB = sA + B_HI_OFF;

        #pragma unroll
        for (int ks = 0; ks < 2; ++ks) {
            const uint32_t koff = ks * 32 + lksl * 16;
            uint32_t ahi[2][4], alo[2][4];
            #pragma unroll
            for (int mt = 0; mt < 2; ++mt) {
                uint32_t ra = sA + (uint32_t)(warp_m * 32 + mt * 16 + l15) * ROWB + koff;
                ldsm4(ahi[mt][0], ahi[mt][1], ahi[mt][2], ahi[mt][3], ra);
                ldsm4(alo[mt][0], alo[mt][1], alo[mt][2], alo[mt][3], ra + A_LO_OFF);
            }
            #pragma unroll
            for (int g = 0; g < 4; ++g) {
                uint32_t rb = sB + (uint32_t)(warp_n * 64 + g * 16 + l15) * ROWB + koff;
                uint32_t bh0, bh1, bh2, bh3, bl0, bl1, bl2, bl3;
                ldsm4(bh0, bh1, bh2, bh3, rb);
                ldsm4(bl0, bl1, bl2, bl3, rb + (B_LO_OFF - B_HI_OFF));
                #pragma unroll
                for (int mt = 0; mt < 2; ++mt) {
                    float* c0 = acc[mt][2 * g];
                    float* c1 = acc[mt][2 * g + 1];
                    mma_bf16(c0, ahi[mt], bh0, bh2);
                    mma_bf16(c1, ahi[mt], bh1, bh3);
                    mma_bf16(c0, ahi[mt], bl0, bl2);
                    mma_bf16(c1, ahi[mt], bl1, bl3);
                    mma_bf16(c0, alo[mt], bh0, bh2);
                    mma_bf16(c1, alo[mt], bh1, bh3);
                }
            }
        }
        __syncthreads();
    }

    // ---------------- epilogue ----------------
    #pragma unroll
    for (int mt = 0; mt < 2; ++mt) {
        #pragma unroll
        for (int h = 0; h < 2; ++h) {
            const int row = bm + warp_m * 32 + mt * 16 + (lane >> 2) + h * 8;
            #pragma unroll
            for (int nt = 0; nt < 8; ++nt) {
                const int col = bn + warp_n * 64 + nt * 8 + ((lane & 3) << 1);
                float v0 = acc[mt][nt][h * 2 + 0];
                float v1 = acc[mt][nt][h * 2 + 1];
                if (mode == 1) {
                    if (col < Nlimit) {
                        float t0 = tanhf(v0 + bias[col]);
                        float t1 = tanhf(v1 + bias[col + 1]);
                        *reinterpret_cast<float2*>(outf + (size_t)row * ldf + col) =
                            make_float2(t0, t1);
                        __nv_bfloat16 h0 = __float2bfloat16(t0);
                        __nv_bfloat16 h1 = __float2bfloat16(t1);
                        __nv_bfloat162 hp; hp.x = h0; hp.y = h1;
                        __nv_bfloat162 lp;
                        lp.x = __float2bfloat16(t0 - __bfloat162float(h0));
                        lp.y = __float2bfloat16(t1 - __bfloat162float(h1));
                        *reinterpret_cast<__nv_bfloat162*>(outHi + (size_t)row * ldhl + col) = hp;
                        *reinterpret_cast<__nv_bfloat162*>(outLo + (size_t)row * ldhl + col) = lp;
                    }
                } else {
                    #pragma unroll
                    for (int e = 0; e < 2; ++e) {
                        int c = col + e;
                        if (c < Nlimit) {
                            float val = (e == 0) ? v0 : v1;
                            int m6 = c / 5, j5 = c - m6 * 5;
                            int kk = (j5 < 3) ? j5 : j5 + 1;
                            float sc = v5[(size_t)row * 5 + j5];
                            outf[(size_t)row * ldf + c] = (val + bias[m6 * 6 + kk]) * sc;
                        }
                    }
                }
            }
        }
    }
}

// ---------------- transpose + bf16 split (optionally compact k%6==3) --------
__global__ __launch_bounds__(256)
void transpose_split(const float* __restrict__ W, int R, int Cstride, int nlimit,
                     __nv_bfloat16* __restrict__ Thi, __nv_bfloat16* __restrict__ Tlo,
                     int ldt, int compact)
{
    __shared__ float ts[32][33];
    const int tx = threadIdx.x, ty = threadIdx.y;   // 32 x 8
    const int n0 = blockIdx.x * 32, k0 = blockIdx.y * 32;
    #pragma unroll
    for (int i = 0; i < 32; i += 8) {
        int k = k0 + ty + i, n = n0 + tx;
        ts[ty + i][tx] = (k < R && n < nlimit) ? W[(size_t)k * Cstride + n] : 0.f;
    }
    __syncthreads();
    #pragma unroll
    for (int i = 0; i < 32; i += 8) {
        int n = n0 + ty + i, k = k0 + tx;
        if (n < nlimit && k < R) {
            int np = n;
            if (compact) {
                int r6 = n % 6;
                if (r6 == 3) continue;
                np = (n / 6) * 5 + (r6 < 3 ? r6 : r6 - 1);
            }
            float val = ts[tx][ty + i];
            __nv_bfloat16 hi = __float2bfloat16(val);
            float lo = val - __bfloat162float(hi);
            Thi[(size_t)np * ldt + k] = hi;
            Tlo[(size_t)np * ldt + k] = __float2bfloat16(lo);
        }
    }
}

// ---------------- h1 = tanh(z @ W1 + b1), SIMT (tiny) ----------------------
__global__ __launch_bounds__(256, 2)
void h1_kernel(const float* __restrict__ A, int lda,
               const float* __restrict__ Bm, int ldb,
               const float* __restrict__ bias,
               __nv_bfloat16* __restrict__ outHi, __nv_bfloat16* __restrict__ outLo)
{
    __shared__ float As[16][128 + 4];
    __shared__ float Bs[16][128 + 4];
    const int tid = threadIdx.x;
    const int bm = blockIdx.y * 128, bn = blockIdx.x * 128;
    const int tx = tid % 16, ty = tid / 16;
    float acc[8][8];
    #pragma unroll
    for (int i = 0; i < 8; ++i)
        #pragma unroll
        for (int j = 0; j < 8; ++j) acc[i][j] = 0.f;

    for (int k0 = 0; k0 < LAT; k0 += 16) {
        #pragma unroll
        for (int i = 0; i < 8; ++i) {
            int idx = tid + i * 256;
            int m = idx / 16, k = idx % 16;
            As[k][m] = A[(size_t)(bm + m) * lda + k0 + k];
        }
        #pragma unroll
        for (int i = 0; i < 8; ++i) {
            int idx = tid + i * 256;
            int k = idx / 128, n = idx % 128;
            Bs[k][n] = Bm[(size_t)(k0 + k) * ldb + bn + n];
        }
        __syncthreads();
        #pragma unroll
        for (int k = 0; k < 16; ++k) {
            float ra[8], rb[8];
            #pragma unroll
            for (int i = 0; i < 8; ++i) ra[i] = As[k][ty * 8 + i];
            #pragma unroll
            for (int j = 0; j < 8; ++j) rb[j] = Bs[k][tx * 8 + j];
            #pragma unroll
            for (int i = 0; i < 8; ++i)
                #pragma unroll
                for (int j = 0; j < 8; ++j) acc[i][j] = fmaf(ra[i], rb[j], acc[i][j]);
        }
        __syncthreads();
    }
    #pragma unroll
    for (int i = 0; i < 8; ++i) {
        int row = bm + ty * 8 + i;
        #pragma unroll
        for (int j = 0; j < 8; ++j) {
            int col = bn + tx * 8 + j;
            float t = tanhf(acc[i][j] + bias[col]);
            __nv_bfloat16 hi = __float2bfloat16(t);
            float lo = t - __bfloat162float(hi);
            size_t o = (size_t)row * HID + col;
            outHi[o] = hi;
            outLo[o] = __float2bfloat16(lo);
        }
    }
}

// ---------------- tail: 12 dot products -> v5 -------------------------------
__global__ __launch_bounds__(128)
void tail_v_kernel(const float* __restrict__ h2,
                   const float* __restrict__ W3,
                   const float* __restrict__ b3,
                   const float* __restrict__ x,
                   float* __restrict__ v5)
{
    const int b = blockIdx.x;
    const int t = threadIdx.x;
    float p[12];
    #pragma unroll
    for (int j = 0; j < 12; ++j) p[j] = 0.f;
    const float* hrow = h2 + (size_t)b * CS;
    for (int c = t; c < CS; c += 128) {
        float hv = hrow[c];
        const float* wr = W3 + (size_t)c * CS + MK;
        #pragma unroll
        for (int j = 0; j < 12; ++j) p[j] = fmaf(hv, wr[j], p[j]);
    }
    __shared__ float red[128];
    __shared__ float dtail[12];
    for (int j = 0; j < 12; ++j) {
        red[t] = p[j];
        __syncthreads();
        for (int s = 64; s > 0; s >>= 1) {
            if (t < s) red[t] += red[t + s];
            __syncthreads();
        }
        if (t == 0) dtail[j] = red[0] + b3[MK + j];
        __syncthreads();
    }
    if (t < 5) {
        int k = (t < 3) ? t : t + 1;
        float s = x[(size_t)(B_SZ - 1) * XCOLS + IN_F];
        float sv = fmaf(s, dtail[k], dtail[k + 6]);
        float r = (k < 3) ? cosf(sv * (float)k) : sinf(sv * (float)(k - 3));
        v5[(size_t)b * 5 + t] = r;
    }
}

// ---------------- final: group-of-5 sums + 16->64 adaptive linear -----------
__global__ __launch_bounds__(256)
void final_kernel(const float* __restrict__ cc,
                  const float* __restrict__ x,
                  float* __restrict__ out)
{
    const int b = blockIdx.x;
    const int t = threadIdx.x;
    __shared__ float row[MK5];
    __shared__ float inp[IN_F];
    const float* src = cc + (size_t)b * MK5;
    for (int i = t; i < MK5; i += 256) row[i] = src[i];
    if (t < IN_F) inp[t] = x[(size_t)b * XCOLS + t];
    __syncthreads();
    if (t < 64) {
        const int o = t;
        float accum = 0.f;
        #pragma unroll
        for (int i = 0; i < IN_F; ++i) {
            const float* g = row + (i * 64 + o) * 5;
            float wsum = ((g[0] + g[1]) + (g[2] + g[3])) + g[4];
            accum = fmaf(inp[i], wsum, accum);
        }
        const float* g = row + (1024 + o) * 5;
        accum += ((g[0] + g[1]) + (g[2] + g[3])) + g[4];
        out[(size_t)b * 64 + o] = accum;
    }
}

// ----------------------------- launch ---------------------------------------
extern "C" void kernel_launch(void* const* d_in, const int* in_sizes, int n_in,
                              void* d_out, int out_size)
{
    const float* x  = (const float*)d_in[0];
    const float* W1 = (const float*)d_in[1];
    const float* b1 = (const float*)d_in[2];
    const float* W2 = (const float*)d_in[3];
    const float* b2 = (const float*)d_in[4];
    const float* W3 = (const float*)d_in[5];
    const float* b3 = (const float*)d_in[6];
    float* out = (float*)d_out;

    __nv_bfloat16 *h1hi, *h1lo, *h2hi, *h2lo, *w2thi, *w2tlo, *w3thi, *w3tlo;
    float *h2f, *cc, *v5;
    cudaGetSymbolAddress((void**)&h1hi, g_h1hi);
    cudaGetSymbolAddress((void**)&h1lo, g_h1lo);
    cudaGetSymbolAddress((void**)&h2f,  g_h2f);
    cudaGetSymbolAddress((void**)&h2hi, g_h2hi);
    cudaGetSymbolAddress((void**)&h2lo, g_h2lo);
    cudaGetSymbolAddress((void**)&w2thi, g_w2thi);
    cudaGetSymbolAddress((void**)&w2tlo, g_w2tlo);
    cudaGetSymbolAddress((void**)&w3thi, g_w3thi);
    cudaGetSymbolAddress((void**)&w3tlo, g_w3tlo);
    cudaGetSymbolAddress((void**)&cc,  g_cc);
    cudaGetSymbolAddress((void**)&v5,  g_v5);

    static bool attr_set = false;
    if (!attr_set) {
        cudaFuncSetAttribute(mma_gemm, cudaFuncAttributeMaxDynamicSharedMemorySize, GEMM_SMEM);
        attr_set = true;
    }

    // 0a) W2^T split: [1024][6540] -> [6540][1024] (pad rows stay zero)
    transpose_split<<<dim3((CS + 31) / 32, (HID + 31) / 32), dim3(32, 8)>>>(
        W2, HID, CS, CS, w2thi, w2tlo, HID, 0);
    // 0b) W3^T split + compact: [6540][6528] -> [5440][6656-ld]
    transpose_split<<<dim3((MK + 31) / 32, (CS + 31) / 32), dim3(32, 8)>>>(
        W3, CS, CS, MK, w3thi, w3tlo, CSP, 1);

    // 1) h1 = tanh(z @ W1 + b1) -> bf16 hi/lo
    h1_kernel<<<dim3(HID / 128, B_SZ / 128), 256>>>(
        x + (IN_F + 1), XCOLS, W1, HID, b1, h1hi, h1lo);

    // 2) h2 = tanh(h1 @ W2 + b2): bf16x3 HMMA, K=1024, N covers 6656
    mma_gemm<<<dim3(CSP / 256, B_SZ / 128), 512, GEMM_SMEM>>>(
        h1hi, h1lo, HID, w2thi, w2tlo, HID, HID / 32,
        b2, nullptr, h2f, h2hi, h2lo, CS, CSP, CS, 1);

    // 3) tail 12 columns -> v5
    tail_v_kernel<<<B_SZ, 128>>>(h2f, W3, b3, x, v5);

    // 4) big GEMM: cc = (h2 @ W3t' + b3) * v5 : K covers 6560, N covers 5632
    mma_gemm<<<dim3(MK5P / 256, B_SZ / 128), 512, GEMM_SMEM>>>(
        h2hi, h2lo, CSP, w3thi, w3tlo, CSP, (CS + 31) / 32,
        b3, v5, cc, nullptr, nullptr, MK5, 0,
        MK5, 2);

    // 5) group-of-5 sums + adaptive linear
    final_kernel<<<B_SZ, 256>>>(cc, x, out);
}